// round 16
// baseline (speedup 1.0000x reference)
#include <cuda_runtime.h>
#include <cuda_bf16.h>
#include <math.h>
#include <stdint.h>

#define Bb   32
#define Tt   128
#define BT   4096
#define DIN  32
#define H1   1024
#define Hh   2048
#define G3   6144
#define PEN  1024
#define Cc   64
#define Pp   4

typedef __nv_bfloat16 bf16;

// ---------------- device globals (no allocation) -----------------------------
__device__ __align__(16) float g_XP[(size_t)BT * G3];
__device__ __align__(16) float g_S [BT * PEN];
__device__ __align__(16) float g_HT[2][Hh * Bb];
__device__ __align__(16) bf16  g_xb  [2][BT * DIN];
__device__ __align__(16) bf16  g_W1b [2][H1 * DIN];
__device__ __align__(16) bf16  g_W2b [2][(size_t)Hh * H1];
__device__ __align__(16) bf16  g_Wihb[2][(size_t)G3 * Hh];
__device__ __align__(16) bf16  g_Whhb[2][(size_t)G3 * Hh];
__device__ __align__(16) bf16  g_W3b [2][(size_t)PEN * Hh];
__device__ __align__(16) bf16  g_A1b [2][(size_t)BT * H1];
__device__ __align__(16) bf16  g_A2b [2][(size_t)BT * Hh];
__device__ __align__(16) bf16  g_Hb  [2][(size_t)BT * Hh];
// packed W stream: per (block,chunk) 8KB tile of 64 rows x 64 cols (swizzled):
//   rows 0-31: W_lo(r,z)   rows 32-47: W_hi(n)   rows 48-63: W_lo(n)
__device__ __align__(16) bf16  g_WstrPk[(size_t)128 * 32 * 4096];
// packed h state: [buf][hi/lo][chunk(32)][b(32)][64] swizzled, 4KB chunks
__device__ __align__(16) bf16  g_hpk[2][2][32 * 32 * 64];
__device__ unsigned g_gen;
__device__ unsigned g_count;

// ---------------- helpers ----------------------------------------------------
__device__ __forceinline__ void split_bf16(float a, uint16_t& h, uint16_t& l) {
    __nv_bfloat16 bh = __float2bfloat16_rn(a);
    float r = a - __bfloat162float(bh);
    __nv_bfloat16 bl = __float2bfloat16_rn(r);
    h = __bfloat16_as_ushort(bh);
    l = __bfloat16_as_ushort(bl);
}
__device__ __forceinline__ uint32_t pack16(uint16_t a, uint16_t b) {
    return (uint32_t)a | ((uint32_t)b << 16);
}
__device__ __forceinline__ void cp16(uint32_t sa, const void* g) {
    asm volatile("cp.async.cg.shared.global [%0], [%1], 16;" :: "r"(sa), "l"(g));
}
#define CP_COMMIT asm volatile("cp.async.commit_group;")
#define CP_WAIT1  asm volatile("cp.async.wait_group 1;")
#define CP_WAIT0  asm volatile("cp.async.wait_group 0;")

__device__ __forceinline__ void ldsm4f(uint32_t* r, const uint16_t* arr, int LD,
                                       int rowBase, int col, int lane) {
    int q = lane >> 3, rr = lane & 7;
    const uint16_t* p = arr + (rowBase + rr + ((q & 1) << 3)) * LD + col + ((q >> 1) << 3);
    uint32_t a = (uint32_t)__cvta_generic_to_shared(p);
    asm volatile("ldmatrix.sync.aligned.m8n8.x4.shared.b16 {%0,%1,%2,%3}, [%4];"
        : "=r"(r[0]), "=r"(r[1]), "=r"(r[2]), "=r"(r[3]) : "r"(a));
}
// ldmatrix from packed 128B-pitch tiles with 16B-unit swizzle u^(row&7)
__device__ __forceinline__ void ldsm4_sw(uint32_t* r, const uint16_t* base,
                                         int rowBase, int kb, int lane) {
    int q = lane >> 3, rr = lane & 7;
    int row = rowBase + rr + ((q & 1) << 3);
    int u = (kb >> 3) + (q >> 1);
    uint32_t a = (uint32_t)__cvta_generic_to_shared(base) + row * 128 + ((u ^ (row & 7)) << 4);
    asm volatile("ldmatrix.sync.aligned.m8n8.x4.shared.b16 {%0,%1,%2,%3}, [%4];"
        : "=r"(r[0]), "=r"(r[1]), "=r"(r[2]), "=r"(r[3]) : "r"(a));
}
__device__ __forceinline__ void ldsm2_sw(uint32_t* r, const uint16_t* base,
                                         int rowBase, int kb, int lane) {
    int l = lane & 15; int q = l >> 3, rr = l & 7;
    int row = rowBase + rr;
    int u = (kb >> 3) + q;
    uint32_t a = (uint32_t)__cvta_generic_to_shared(base) + row * 128 + ((u ^ (row & 7)) << 4);
    asm volatile("ldmatrix.sync.aligned.m8n8.x2.shared.b16 {%0,%1}, [%2];"
        : "=r"(r[0]), "=r"(r[1]) : "r"(a));
}
#define MMA4(c, af, b0, b1) \
    asm volatile("mma.sync.aligned.m16n8k16.row.col.f32.bf16.bf16.f32 " \
        "{%0,%1,%2,%3},{%4,%5,%6,%7},{%8,%9},{%0,%1,%2,%3};" \
        : "+f"((c)[0]),"+f"((c)[1]),"+f"((c)[2]),"+f"((c)[3]) \
        : "r"((af)[0]),"r"((af)[1]),"r"((af)[2]),"r"((af)[3]),"r"(b0),"r"(b1))

__device__ __forceinline__ float sigmoidf_(float x) { return 1.0f / (1.0f + expf(-x)); }

// ---------------- fused: all fp32->bf16 hi/lo conversions + init -------------
#define CONV_BLOCKS 14416
__global__ __launch_bounds__(256)
void convert_all(const float* __restrict__ x,  const float* __restrict__ W1,
                 const float* __restrict__ W2, const float* __restrict__ Wih,
                 const float* __restrict__ Whh,const float* __restrict__ W3,
                 float* __restrict__ out, int out_size) {
    int gid = blockIdx.x * 256 + threadIdx.x;
    if (gid < Hh * Bb) {
        g_HT[0][gid] = 0.0f;
        bf16 z = __ushort_as_bfloat16((uint16_t)0);
        g_hpk[0][0][2 * gid] = z; g_hpk[0][0][2 * gid + 1] = z;
        g_hpk[0][1][2 * gid] = z; g_hpk[0][1][2 * gid + 1] = z;
        int tail = 28672 + gid;
        if (tail < out_size) out[tail] = 0.0f;
        if (gid == 0) { g_gen = 0u; g_count = 0u; }
    }
    const float* src; bf16 *hi, *lo; int off;
    if      (gid < 16384)   { src = x;   hi = g_xb[0];   lo = g_xb[1];   off = gid; }
    else if (gid < 20480)   { src = W1;  hi = g_W1b[0];  lo = g_W1b[1];  off = gid - 16384; }
    else if (gid < 282624)  { src = W2;  hi = g_W2b[0];  lo = g_W2b[1];  off = gid - 20480; }
    else if (gid < 1855488) { src = Wih; hi = g_Wihb[0]; lo = g_Wihb[1]; off = gid - 282624; }
    else if (gid < 3428352) { src = Whh; hi = g_Whhb[0]; lo = g_Whhb[1]; off = gid - 1855488; }
    else                    { src = W3;  hi = g_W3b[0];  lo = g_W3b[1];  off = gid - 3428352; }
    size_t base = (size_t)off * 8;
    float4 v0 = *(const float4*)(src + base);
    float4 v1 = *(const float4*)(src + base + 4);
    uint16_t h[8], l[8];
    split_bf16(v0.x,h[0],l[0]); split_bf16(v0.y,h[1],l[1]);
    split_bf16(v0.z,h[2],l[2]); split_bf16(v0.w,h[3],l[3]);
    split_bf16(v1.x,h[4],l[4]); split_bf16(v1.y,h[5],l[5]);
    split_bf16(v1.z,h[6],l[6]); split_bf16(v1.w,h[7],l[7]);
    uint4 ph, pl;
    ph.x = pack16(h[0],h[1]); ph.y = pack16(h[2],h[3]);
    ph.z = pack16(h[4],h[5]); ph.w = pack16(h[6],h[7]);
    pl.x = pack16(l[0],l[1]); pl.y = pack16(l[2],l[3]);
    pl.z = pack16(l[4],l[5]); pl.w = pack16(l[6],l[7]);
    *(uint4*)(hi + base) = ph;
    *(uint4*)(lo + base) = pl;
}

// ---------------- pack streamed-W into per-(block,chunk) 8KB tiles -----------
__global__ __launch_bounds__(256)
void pack_wstr() {
    int gid = blockIdx.x * 256 + threadIdx.x;        // 2,097,152 16B-units
    int bk   = gid >> 14;
    int rem  = gid & 16383;
    int c    = rem >> 9;
    int rem2 = rem & 511;
    int r    = rem2 >> 3;
    int pu   = rem2 & 7;
    int u    = pu ^ (r & 7);
    int jbase = bk * 16;
    const bf16* src; int grow;
    if (r < 32)      { src = g_Whhb[1]; grow = (r >> 4) * Hh + jbase + (r & 15); }
    else if (r < 48) { src = g_Whhb[0]; grow = 2 * Hh + jbase + (r - 32); }
    else             { src = g_Whhb[1]; grow = 2 * Hh + jbase + (r - 48); }
    const uint4* s = (const uint4*)(src + (size_t)grow * Hh + c * 64 + u * 8);
    uint4* d = (uint4*)(g_WstrPk + ((size_t)(bk * 32 + c)) * 4096 + r * 64 + pu * 8);
    *d = *s;
}

// ---------------- 3-pass split-bf16 tensor-core GEMM -------------------------
// NOW __launch_bounds__(256, 2): force regs<=128 so 2 blocks/SM co-reside.
#define SLD 40
#define GEMM_SMEM (2 * 4 * 128 * SLD * 2)   // 81920 B

template<bool RELU, bool BF16OUT>
__global__ __launch_bounds__(256, 2)
void gemm3p(const bf16* __restrict__ Ah, const bf16* __restrict__ Al,
            const bf16* __restrict__ Wh, const bf16* __restrict__ Wl,
            const float* __restrict__ bias,
            float* __restrict__ outF, bf16* __restrict__ outH, bf16* __restrict__ outL,
            int M, int N, int K) {
    extern __shared__ char raw[];
    uint16_t* sm = (uint16_t*)raw;
    const int tid = threadIdx.x, lane = tid & 31, wid = tid >> 5;
    const int wm = (wid & 3) * 32, wn = (wid >> 2) * 64;
    const int n0 = blockIdx.x * 128, m0 = blockIdx.y * 128;
    const int gr = lane >> 2, c2 = (lane & 3) * 2;
    const int row0 = tid >> 2, seg = (tid & 3) << 3;
    const uint32_t smBase = (uint32_t)__cvta_generic_to_shared(sm);

    const bf16* gAh = Ah + (size_t)m0 * K;
    const bf16* gAl = Al + (size_t)m0 * K;
    const bf16* gWh = Wh + (size_t)n0 * K;
    const bf16* gWl = Wl + (size_t)n0 * K;

    float acc[2][8][4];
#pragma unroll
    for (int i = 0; i < 2; i++)
#pragma unroll
        for (int j = 0; j < 8; j++)
#pragma unroll
            for (int e = 0; e < 4; e++) acc[i][j][e] = 0.0f;

#define GISS(ptr, aidx, rep, s, k0) \
    cp16(smBase + (uint32_t)((((s)*4+(aidx))*(128*SLD)) + (row0 + (rep)*64)*SLD + seg)*2, \
         (ptr) + (size_t)(row0 + (rep)*64) * K + (k0) + seg)
#define GEMM_ISSUE(s, k0) do { \
    GISS(gAh, 0, 0, s, k0); GISS(gAh, 0, 1, s, k0); \
    GISS(gAl, 1, 0, s, k0); GISS(gAl, 1, 1, s, k0); \
    GISS(gWh, 2, 0, s, k0); GISS(gWh, 2, 1, s, k0); \
    GISS(gWl, 3, 0, s, k0); GISS(gWl, 3, 1, s, k0); } while (0)

    const int nch = K >> 5;
    GEMM_ISSUE(0, 0);
    CP_COMMIT;
#pragma unroll 1
    for (int c = 0; c < nch; c++) {
        if (c + 1 < nch) { GEMM_ISSUE((c + 1) & 1, (c + 1) << 5); CP_COMMIT; CP_WAIT1; }
        else { CP_WAIT0; }
        __syncthreads();
        const int st = c & 1;
        const uint16_t* Ah_s = sm + (st * 4 + 0) * (128 * SLD);
        const uint16_t* Al_s = sm + (st * 4 + 1) * (128 * SLD);
        const uint16_t* Wh_s = sm + (st * 4 + 2) * (128 * SLD);
        const uint16_t* Wl_s = sm + (st * 4 + 3) * (128 * SLD);
#pragma unroll
        for (int ks = 0; ks < 2; ks++) {
            const int kb = ks * 16;
            uint32_t ahf[2][4], alf[2][4];
#pragma unroll
            for (int mt = 0; mt < 2; mt++) {
                ldsm4f(ahf[mt], Ah_s, SLD, wm + mt * 16, kb, lane);
                ldsm4f(alf[mt], Al_s, SLD, wm + mt * 16, kb, lane);
            }
#pragma unroll
            for (int p = 0; p < 4; p++) {
                uint32_t bh[4], bl[4];
                ldsm4f(bh, Wh_s, SLD, wn + p * 16, kb, lane);
                ldsm4f(bl, Wl_s, SLD, wn + p * 16, kb, lane);
#pragma unroll
                for (int e = 0; e < 2; e++) {
                    const int nt = p * 2 + e;
#pragma unroll
                    for (int mt = 0; mt < 2; mt++) {
                        MMA4(acc[mt][nt], ahf[mt], bh[e], bh[2 + e]);
                        MMA4(acc[mt][nt], ahf[mt], bl[e], bl[2 + e]);
                        MMA4(acc[mt][nt], alf[mt], bh[e], bh[2 + e]);
                    }
                }
            }
        }
        __syncthreads();
    }

#pragma unroll
    for (int mt = 0; mt < 2; mt++) {
        const int r = m0 + wm + mt * 16 + gr;
#pragma unroll
        for (int nt = 0; nt < 8; nt++) {
            const int cb = n0 + wn + nt * 8 + c2;
            float bx = bias[cb], by = bias[cb + 1];
            float v0 = acc[mt][nt][0] + bx;
            float v1 = acc[mt][nt][1] + by;
            float v2 = acc[mt][nt][2] + bx;
            float v3 = acc[mt][nt][3] + by;
            if (RELU) {
                v0 = fmaxf(v0, 0.0f); v1 = fmaxf(v1, 0.0f);
                v2 = fmaxf(v2, 0.0f); v3 = fmaxf(v3, 0.0f);
            }
            if (BF16OUT) {
                uint16_t h0,l0,h1,l1;
                split_bf16(v0,h0,l0); split_bf16(v1,h1,l1);
                *(uint32_t*)(outH + (size_t)r * N + cb) = pack16(h0,h1);
                *(uint32_t*)(outL + (size_t)r * N + cb) = pack16(l0,l1);
                split_bf16(v2,h0,l0); split_bf16(v3,h1,l1);
                *(uint32_t*)(outH + (size_t)(r + 8) * N + cb) = pack16(h0,h1);
                *(uint32_t*)(outL + (size_t)(r + 8) * N + cb) = pack16(l0,l1);
            } else {
                *(float2*)(outF + (size_t)r * N + cb)       = make_float2(v0, v1);
                *(float2*)(outF + (size_t)(r + 8) * N + cb) = make_float2(v2, v3);
            }
        }
    }
}

// ---------------- persistent GRU: 5-deep TMA pipeline, 2 chunks per sync -----
// 128 blocks x 384 threads. Resident: W_hi gates r,z (chunk-major swizzled).
// Per chunk: 8KB W tile + 2x4KB h streamed, 5 stages. Three independent
// accumulators (one per split pass). TWO chunks are processed per
// __syncthreads to halve barrier overhead.
#define NST 5
#define RES_ELEMS 65536
#define STG_ELEMS 8192
#define STG_B 16384
#define GRU_SMEM ((RES_ELEMS + NST * STG_ELEMS) * 2 + 48 * 33 * 4)  // 219328

__global__ __launch_bounds__(384)
void gru_persist(const float* __restrict__ bhh) {
    extern __shared__ char raw[];
    uint16_t* sm = (uint16_t*)raw;
    __shared__ __align__(8) uint64_t s_mbar[NST];
    const int tid = threadIdx.x, lane = tid & 31, wid = tid >> 5;
    const int nt = wid % 6, mt = wid / 6;
    const int jbase = blockIdx.x * 16;
    const int gr = lane >> 2, cc2 = (lane & 3) * 2;
    const uint32_t smBase = (uint32_t)__cvta_generic_to_shared(sm);
    const uint32_t stgBase = smBase + RES_ELEMS * 2;
    float* hp = (float*)(raw + (RES_ELEMS + NST * STG_ELEMS) * 2);
    const uint32_t mbarBase = (uint32_t)__cvta_generic_to_shared(s_mbar);

    // prologue: pack resident W_{r,z} hi into chunk-major swizzled smem
    for (int i = tid; i < 8192; i += 384) {
        int c = i >> 8; int rem = i & 255;
        int r = rem >> 3; int pu = rem & 7;
        int u = pu ^ (r & 7);
        int grow = (r >> 4) * Hh + jbase + (r & 15);
        *(uint4*)(sm + (size_t)(c * 32 + r) * 64 + pu * 8) =
            *(const uint4*)(g_Whhb[0] + (size_t)grow * Hh + c * 64 + u * 8);
    }
    if (tid == 0) {
#pragma unroll
        for (int s = 0; s < NST; s++)
            asm volatile("mbarrier.init.shared.b64 [%0], 1;" :: "r"(mbarBase + s * 8) : "memory");
    }
    __syncthreads();

    const bf16* wstrB = g_WstrPk + (size_t)blockIdx.x * 32 * 4096;
    uint32_t phMask = 0;

    auto rearm = [&](int s) {
        asm volatile("mbarrier.arrive.expect_tx.shared.b64 _, [%0], %1;"
            :: "r"(mbarBase + s * 8), "r"((uint32_t)STG_B) : "memory");
    };
    auto issueW = [&](int s, int ch) {
        asm volatile("cp.async.bulk.shared::cta.global.mbarrier::complete_tx::bytes [%0], [%1], %2, [%3];"
            :: "r"(stgBase + s * STG_B), "l"((const void*)(wstrB + (size_t)ch * 4096)),
               "r"(8192u), "r"(mbarBase + s * 8) : "memory");
    };
    auto issueH = [&](int s, int ch, const bf16* hh, const bf16* hl) {
        asm volatile("cp.async.bulk.shared::cta.global.mbarrier::complete_tx::bytes [%0], [%1], %2, [%3];"
            :: "r"(stgBase + s * STG_B + 8192u), "l"((const void*)(hh + ch * 2048)),
               "r"(4096u), "r"(mbarBase + s * 8) : "memory");
        asm volatile("cp.async.bulk.shared::cta.global.mbarrier::complete_tx::bytes [%0], [%1], %2, [%3];"
            :: "r"(stgBase + s * STG_B + 12288u), "l"((const void*)(hl + ch * 2048)),
               "r"(4096u), "r"(mbarBase + s * 8) : "memory");
    };
    auto wait_stage = [&](int s) {
        uint32_t bar = mbarBase + s * 8;
        uint32_t p = (phMask >> s) & 1u;
        uint32_t done;
        do {
            asm volatile("{\n\t.reg .pred P;\n\t"
                "mbarrier.try_wait.parity.shared.b64 P, [%1], %2, 0x989680;\n\t"
                "selp.b32 %0, 1, 0, P;\n\t}"
                : "=r"(done) : "r"(bar), "r"(p) : "memory");
        } while (!done);
        phMask ^= (1u << s);
    };

    // step-0 prefetch: all 5 stages (W + h)
    if (tid == 0) {
        const bf16* h0 = g_hpk[0][0];
        const bf16* l0 = g_hpk[0][1];
#pragma unroll
        for (int s = 0; s < NST; s++) { rearm(s); issueW(s, s); issueH(s, s, h0, l0); }
    }

#pragma unroll 1
    for (int t = 0; t < Tt; t++) {
        const bf16* hHi = g_hpk[t & 1][0];
        const bf16* hLo = g_hpk[t & 1][1];

        float accA[4] = {0.f, 0.f, 0.f, 0.f};
        float accB[4] = {0.f, 0.f, 0.f, 0.f};
        float accC[4] = {0.f, 0.f, 0.f, 0.f};
        int s = 0;

        // per-chunk mma body
        auto do_chunk = [&](int c, int st) {
            const uint16_t* Wst  = sm + RES_ELEMS + st * STG_ELEMS;
            const uint16_t* WnHi = Wst + 2048;
            const uint16_t* WnLo = Wst + 3072;
            const uint16_t* Hh_s = Wst + 4096;
            const uint16_t* Hl_s = Wst + 6144;
            const uint16_t* Wres = sm + c * 2048;
#pragma unroll
            for (int ks = 0; ks < 4; ks++) {
                const int kb = ks * 16;
                uint32_t ah[4], al[4], bh[2], bl[2];
                ldsm4_sw(ah, Hh_s, mt * 16, kb, lane);
                ldsm4_sw(al, Hl_s, mt * 16, kb, lane);
                if (nt < 4) {
                    ldsm2_sw(bh, Wres, nt * 8, kb, lane);
                    ldsm2_sw(bl, Wst,  nt * 8, kb, lane);
                } else {
                    ldsm2_sw(bh, WnHi, (nt - 4) * 8, kb, lane);
                    ldsm2_sw(bl, WnLo, (nt - 4) * 8, kb, lane);
                }
                MMA4(accA, ah, bh[0], bh[1]);
                MMA4(accB, ah, bl[0], bl[1]);
                MMA4(accC, al, bh[0], bh[1]);
            }
        };
        auto refill = [&](int st, int c) {
            int n = c + NST;
            if (n < 32) { rearm(st); issueW(st, n); issueH(st, n, hHi, hLo); }
            else if (t < Tt - 1) { rearm(st); issueW(st, st); }   // next step chunk st
        };

#pragma unroll 1
        for (int c = 0; c < 32; c += 2) {
            int s0 = s;
            int s1 = (s0 == NST - 1) ? 0 : s0 + 1;
            wait_stage(s0);
            do_chunk(c, s0);
            wait_stage(s1);
            do_chunk(c + 1, s1);
            __syncthreads();                       // one barrier per TWO chunks
            if (tid == 0) { refill(s0, c); refill(s1, c + 1); }
            s = (s1 == NST - 1) ? 0 : s1 + 1;
        }

        // combine passes, scatter into hp[gate_row][batch], stride 33
        {
            int col = nt * 8 + cc2, row = mt * 16 + gr;
            hp[col * 33 + row]           = accA[0] + accB[0] + accC[0];
            hp[(col + 1) * 33 + row]     = accA[1] + accB[1] + accC[1];
            hp[col * 33 + row + 8]       = accA[2] + accB[2] + accC[2];
            hp[(col + 1) * 33 + row + 8] = accA[3] + accB[3] + accC[3];
        }
        __syncthreads();

        const float* HTprev = g_HT[t & 1];
        float* HTnext = g_HT[(t & 1) ^ 1];
        bf16* nHi = g_hpk[(t & 1) ^ 1][0];
        bf16* nLo = g_hpk[(t & 1) ^ 1][1];
#pragma unroll
        for (int i = 0; i < 2; i++) {
            int oi = tid + i * 384;
            if (oi < 512) {
                int b = oi & 31, jj = oi >> 5, j = jbase + jj;
                size_t xoff = ((size_t)b * Tt + t) * G3 + j;
                float xr = g_XP[xoff];
                float xz = g_XP[xoff + Hh];
                float xn = g_XP[xoff + 2 * Hh];
                float hr = hp[jj * 33 + b]        + bhh[j];
                float hz = hp[(16 + jj) * 33 + b] + bhh[Hh + j];
                float hn = hp[(32 + jj) * 33 + b] + bhh[2 * Hh + j];
                float r = sigmoidf_(xr + hr);
                float z = sigmoidf_(xz + hz);
                float n = tanhf(xn + r * hn);
                float hprev = HTprev[j * 32 + b];
                float hnew = (1.0f - z) * n + z * hprev;
                HTnext[j * 32 + b] = hnew;
                uint16_t hh, hl;
                split_bf16(hnew, hh, hl);
                int ck = j >> 6, k = j & 63, u = k >> 3;
                size_t e = ((size_t)((ck << 5) + b) << 6) +
                           (size_t)(((u ^ (b & 7)) << 3) + (k & 7));
                nHi[e] = __ushort_as_bfloat16(hh);
                nLo[e] = __ushort_as_bfloat16(hl);
                g_Hb[0][((size_t)b * Tt + t) * Hh + j] = __ushort_as_bfloat16(hh);
                g_Hb[1][((size_t)b * Tt + t) * Hh + j] = __ushort_as_bfloat16(hl);
            }
        }

        // global barrier between steps (order gate writes before next h TMAs)
        asm volatile("fence.proxy.async;" ::: "memory");
        __threadfence();
        __syncthreads();
        if (tid == 0) {
            unsigned a = atomicAdd(&g_count, 1u);
            if (a == 127u) {
                g_count = 0u;
                __threadfence();
                atomicAdd(&g_gen, 1u);
            } else {
                while (*(volatile unsigned*)&g_gen <= (unsigned)t) __nanosleep(32);
            }
            // release h TMAs for next step's chunks 0..4 (W already in flight)
            if (t < Tt - 1) {
                const bf16* nh = g_hpk[(t + 1) & 1][0];
                const bf16* nl = g_hpk[(t + 1) & 1][1];
#pragma unroll
                for (int s2 = 0; s2 < NST; s2++) issueH(s2, s2, nh, nl);
            }
        }
        __syncthreads();
    }
}

// ---------------- heads ------------------------------------------------------
__global__ __launch_bounds__(128)
void heads_kernel(const int* __restrict__ labels,
                  const float* __restrict__ W4, const float* __restrict__ b4,
                  const float* __restrict__ W5, const float* __restrict__ b5,
                  const float* __restrict__ W6, const float* __restrict__ b6,
                  const float* __restrict__ Wp, const float* __restrict__ bp,
                  float* __restrict__ out) {
    const int bt   = blockIdx.x;
    const int b    = bt >> 7;
    const int t    = bt & 127;
    const int lane = threadIdx.x & 31;
    const int w    = threadIdx.x >> 5;
    const int lab  = labels[b];
    const float4* s4 = (const float4*)(g_S + (size_t)bt * PEN);

    for (int hh = w; hh < 7; hh += 4) {
        const float* Wrow;
        float bias;
        if (hh == 0)      { Wrow = W4 + (size_t)lab * PEN; bias = b4[lab]; }
        else if (hh == 1) { Wrow = W5 + (size_t)lab * PEN; bias = b5[lab]; }
        else if (hh == 2) { Wrow = W6 + (size_t)lab * PEN; bias = b6[lab]; }
        else {
            int p = hh - 3;
            Wrow = Wp + ((size_t)p * Cc + lab) * PEN;
            bias = bp[p * Cc + lab];
        }
        const float4* w4 = (const float4*)Wrow;
        float acc = 0.0f;
        for (int q = lane; q < PEN / 4; q += 32) {
            float4 sv = s4[q];
            float4 wv = w4[q];
            acc += sv.x * wv.x + sv.y * wv.y + sv.z * wv.z + sv.w * wv.w;
        }
#pragma unroll
        for (int off = 16; off > 0; off >>= 1)
            acc += __shfl_down_sync(0xffffffffu, acc, off);
        if (lane == 0) {
            float v = acc + bias;
            if (hh < 3) out[hh * BT + bt] = v;
            else {
                int p = hh - 3;
                out[3 * BT + ((size_t)p * Bb + b) * Tt + t] = 1.0f / (1.0f + expf(-v));
            }
        }
    }
}

// ---------------- launch -----------------------------------------------------
extern "C" void kernel_launch(void* const* d_in, const int* in_sizes, int n_in,
                              void* d_out, int out_size) {
    const float* x    = (const float*)d_in[0];
    const int*   lab  = (const int*)  d_in[1];
    const float* W1   = (const float*)d_in[2];
    const float* b1   = (const float*)d_in[3];
    const float* W2   = (const float*)d_in[4];
    const float* b2   = (const float*)d_in[5];
    const float* W_ih = (const float*)d_in[6];
    const float* b_ih = (const float*)d_in[7];
    const float* W_hh = (const float*)d_in[8];
    const float* b_hh = (const float*)d_in[9];
    const float* W3   = (const float*)d_in[10];
    const float* b3   = (const float*)d_in[11];
    const float* W4   = (const float*)d_in[12];
    const float* b4   = (const float*)d_in[13];
    const float* W5   = (const float*)d_in[14];
    const float* b5   = (const float*)d_in[15];
    const float* W6   = (const float*)d_in[16];
    const float* b6   = (const float*)d_in[17];
    const float* Wp   = (const float*)d_in[18];
    const float* bp   = (const float*)d_in[19];
    float* out = (float*)d_out;

    float *XP, *S;
    bf16 *xb[2], *W1b[2], *W2b[2], *Wihb[2], *W3b[2], *A1b[2], *A2b[2], *Hbp[2];
    cudaGetSymbolAddress((void**)&XP, g_XP);
    cudaGetSymbolAddress((void**)&S,  g_S);
    {
        char* p;
        cudaGetSymbolAddress((void**)&p, g_xb);
        xb[0] = (bf16*)p; xb[1] = xb[0] + BT * DIN;
        cudaGetSymbolAddress((void**)&p, g_W1b);
        W1b[0] = (bf16*)p; W1b[1] = W1b[0] + H1 * DIN;
        cudaGetSymbolAddress((void**)&p, g_W2b);
        W2b[0] = (bf16*)p; W2b[1] = W2b[0] + (size_t)Hh * H1;
        cudaGetSymbolAddress((void**)&p, g_Wihb);
        Wihb[0] = (bf16*)p; Wihb[1] = Wihb[0] + (size_t)G3 * Hh;
        cudaGetSymbolAddress((void**)&p, g_W3b);
        W3b[0] = (bf16*)p; W3b[1] = W3b[0] + (size_t)PEN * Hh;
        cudaGetSymbolAddress((void**)&p, g_A1b);
        A1b[0] = (bf16*)p; A1b[1] = A1b[0] + (size_t)BT * H1;
        cudaGetSymbolAddress((void**)&p, g_A2b);
        A2b[0] = (bf16*)p; A2b[1] = A2b[0] + (size_t)BT * Hh;
        cudaGetSymbolAddress((void**)&p, g_Hb);
        Hbp[0] = (bf16*)p; Hbp[1] = Hbp[0] + (size_t)BT * Hh;
    }

    cudaFuncSetAttribute(gemm3p<true,  true >, cudaFuncAttributeMaxDynamicSharedMemorySize, GEMM_SMEM);
    cudaFuncSetAttribute(gemm3p<false, false>, cudaFuncAttributeMaxDynamicSharedMemorySize, GEMM_SMEM);
    cudaFuncSetAttribute(gemm3p<true,  false>, cudaFuncAttributeMaxDynamicSharedMemorySize, GEMM_SMEM);
    cudaFuncSetAttribute(gru_persist, cudaFuncAttributeMaxDynamicSharedMemorySize, GRU_SMEM);

    // launch 0: all conversions + init (fused)
    convert_all<<<CONV_BLOCKS, 256>>>(x, W1, W2, W_ih, W_hh, W3, out, out_size);
    // launch 1: pack streamed GRU weights
    pack_wstr<<<8192, 256>>>();
    // launch 2: layer1
    gemm3p<true, true><<<dim3(H1 / 128, BT / 128), 256, GEMM_SMEM>>>(
        xb[0], xb[1], W1b[0], W1b[1], b1, nullptr, A1b[0], A1b[1], BT, H1, DIN);
    // launch 3: layer2
    gemm3p<true, true><<<dim3(Hh / 128, BT / 128), 256, GEMM_SMEM>>>(
        A1b[0], A1b[1], W2b[0], W2b[1], b2, nullptr, A2b[0], A2b[1], BT, Hh, H1);
    // launch 4: xp
    gemm3p<false, false><<<dim3(G3 / 128, BT / 128), 256, GEMM_SMEM>>>(
        A2b[0], A2b[1], Wihb[0], Wihb[1], b_ih, XP, nullptr, nullptr, BT, G3, Hh);
    // launch 5: GRU (profiler target)
    gru_persist<<<128, 384, GRU_SMEM>>>(b_hh);
    // launch 6: layer3
    gemm3p<true, false><<<dim3(PEN / 128, BT / 128), 256, GEMM_SMEM>>>(
        Hbp[0], Hbp[1], W3b[0], W3b[1], b3, S, nullptr, nullptr, BT, PEN, Hh);
    // launch 7: heads
    heads_kernel<<<BT, 128>>>(lab, W4, b4, W5, b5, W6, b6, Wp, bp, out);
}

// round 17
// speedup vs baseline: 1.4985x; 1.4985x over previous
#include <cuda_runtime.h>
#include <cuda_bf16.h>
#include <math.h>
#include <stdint.h>

#define Bb   32
#define Tt   128
#define BT   4096
#define DIN  32
#define H1   1024
#define Hh   2048
#define G3   6144
#define PEN  1024
#define Cc   64
#define Pp   4

typedef __nv_bfloat16 bf16;

// ---------------- device globals (no allocation) -----------------------------
__device__ __align__(16) float g_XP[(size_t)BT * G3];
__device__ __align__(16) float g_S [BT * PEN];
__device__ __align__(16) float g_HT[2][Bb * Hh];     // [buf][b][j]  (b-major!)
__device__ __align__(16) bf16  g_xb  [2][BT * DIN];
__device__ __align__(16) bf16  g_W1b [2][H1 * DIN];
__device__ __align__(16) bf16  g_W2b [2][(size_t)Hh * H1];
__device__ __align__(16) bf16  g_Wihb[2][(size_t)G3 * Hh];
__device__ __align__(16) bf16  g_Whhb[2][(size_t)G3 * Hh];
__device__ __align__(16) bf16  g_W3b [2][(size_t)PEN * Hh];
__device__ __align__(16) bf16  g_A1b [2][(size_t)BT * H1];
__device__ __align__(16) bf16  g_A2b [2][(size_t)BT * Hh];
__device__ __align__(16) bf16  g_Hb  [2][(size_t)BT * Hh];
// packed W stream: per (block,chunk) 8KB tile of 64 rows x 64 cols (swizzled):
//   rows 0-31: W_lo(r,z)   rows 32-47: W_hi(n)   rows 48-63: W_lo(n)
__device__ __align__(16) bf16  g_WstrPk[(size_t)128 * 32 * 4096];
// packed h state: [buf][hi/lo][chunk(32)][b(32)][64] swizzled, 4KB chunks
__device__ __align__(16) bf16  g_hpk[2][2][32 * 32 * 64];
__device__ unsigned g_gen;
__device__ unsigned g_count;

// ---------------- helpers ----------------------------------------------------
__device__ __forceinline__ void split_bf16(float a, uint16_t& h, uint16_t& l) {
    __nv_bfloat16 bh = __float2bfloat16_rn(a);
    float r = a - __bfloat162float(bh);
    __nv_bfloat16 bl = __float2bfloat16_rn(r);
    h = __bfloat16_as_ushort(bh);
    l = __bfloat16_as_ushort(bl);
}
__device__ __forceinline__ uint32_t pack16(uint16_t a, uint16_t b) {
    return (uint32_t)a | ((uint32_t)b << 16);
}
__device__ __forceinline__ void cp16(uint32_t sa, const void* g) {
    asm volatile("cp.async.cg.shared.global [%0], [%1], 16;" :: "r"(sa), "l"(g));
}
#define CP_COMMIT asm volatile("cp.async.commit_group;")
#define CP_WAIT1  asm volatile("cp.async.wait_group 1;")
#define CP_WAIT0  asm volatile("cp.async.wait_group 0;")

__device__ __forceinline__ void ldsm4f(uint32_t* r, const uint16_t* arr, int LD,
                                       int rowBase, int col, int lane) {
    int q = lane >> 3, rr = lane & 7;
    const uint16_t* p = arr + (rowBase + rr + ((q & 1) << 3)) * LD + col + ((q >> 1) << 3);
    uint32_t a = (uint32_t)__cvta_generic_to_shared(p);
    asm volatile("ldmatrix.sync.aligned.m8n8.x4.shared.b16 {%0,%1,%2,%3}, [%4];"
        : "=r"(r[0]), "=r"(r[1]), "=r"(r[2]), "=r"(r[3]) : "r"(a));
}
// ldmatrix from packed 128B-pitch tiles with 16B-unit swizzle u^(row&7)
__device__ __forceinline__ void ldsm4_sw(uint32_t* r, const uint16_t* base,
                                         int rowBase, int kb, int lane) {
    int q = lane >> 3, rr = lane & 7;
    int row = rowBase + rr + ((q & 1) << 3);
    int u = (kb >> 3) + (q >> 1);
    uint32_t a = (uint32_t)__cvta_generic_to_shared(base) + row * 128 + ((u ^ (row & 7)) << 4);
    asm volatile("ldmatrix.sync.aligned.m8n8.x4.shared.b16 {%0,%1,%2,%3}, [%4];"
        : "=r"(r[0]), "=r"(r[1]), "=r"(r[2]), "=r"(r[3]) : "r"(a));
}
__device__ __forceinline__ void ldsm2_sw(uint32_t* r, const uint16_t* base,
                                         int rowBase, int kb, int lane) {
    int l = lane & 15; int q = l >> 3, rr = l & 7;
    int row = rowBase + rr;
    int u = (kb >> 3) + q;
    uint32_t a = (uint32_t)__cvta_generic_to_shared(base) + row * 128 + ((u ^ (row & 7)) << 4);
    asm volatile("ldmatrix.sync.aligned.m8n8.x2.shared.b16 {%0,%1}, [%2];"
        : "=r"(r[0]), "=r"(r[1]) : "r"(a));
}
#define MMA4(c, af, b0, b1) \
    asm volatile("mma.sync.aligned.m16n8k16.row.col.f32.bf16.bf16.f32 " \
        "{%0,%1,%2,%3},{%4,%5,%6,%7},{%8,%9},{%0,%1,%2,%3};" \
        : "+f"((c)[0]),"+f"((c)[1]),"+f"((c)[2]),"+f"((c)[3]) \
        : "r"((af)[0]),"r"((af)[1]),"r"((af)[2]),"r"((af)[3]),"r"(b0),"r"(b1))

__device__ __forceinline__ float sigmoidf_(float x) { return 1.0f / (1.0f + expf(-x)); }

// ---------------- fused: all fp32->bf16 hi/lo conversions + init -------------
#define CONV_BLOCKS 14416
__global__ __launch_bounds__(256)
void convert_all(const float* __restrict__ x,  const float* __restrict__ W1,
                 const float* __restrict__ W2, const float* __restrict__ Wih,
                 const float* __restrict__ Whh,const float* __restrict__ W3,
                 float* __restrict__ out, int out_size) {
    int gid = blockIdx.x * 256 + threadIdx.x;
    if (gid < Hh * Bb) {
        g_HT[0][gid] = 0.0f;
        bf16 z = __ushort_as_bfloat16((uint16_t)0);
        g_hpk[0][0][2 * gid] = z; g_hpk[0][0][2 * gid + 1] = z;
        g_hpk[0][1][2 * gid] = z; g_hpk[0][1][2 * gid + 1] = z;
        int tail = 28672 + gid;
        if (tail < out_size) out[tail] = 0.0f;
        if (gid == 0) { g_gen = 0u; g_count = 0u; }
    }
    const float* src; bf16 *hi, *lo; int off;
    if      (gid < 16384)   { src = x;   hi = g_xb[0];   lo = g_xb[1];   off = gid; }
    else if (gid < 20480)   { src = W1;  hi = g_W1b[0];  lo = g_W1b[1];  off = gid - 16384; }
    else if (gid < 282624)  { src = W2;  hi = g_W2b[0];  lo = g_W2b[1];  off = gid - 20480; }
    else if (gid < 1855488) { src = Wih; hi = g_Wihb[0]; lo = g_Wihb[1]; off = gid - 282624; }
    else if (gid < 3428352) { src = Whh; hi = g_Whhb[0]; lo = g_Whhb[1]; off = gid - 1855488; }
    else                    { src = W3;  hi = g_W3b[0];  lo = g_W3b[1];  off = gid - 3428352; }
    size_t base = (size_t)off * 8;
    float4 v0 = *(const float4*)(src + base);
    float4 v1 = *(const float4*)(src + base + 4);
    uint16_t h[8], l[8];
    split_bf16(v0.x,h[0],l[0]); split_bf16(v0.y,h[1],l[1]);
    split_bf16(v0.z,h[2],l[2]); split_bf16(v0.w,h[3],l[3]);
    split_bf16(v1.x,h[4],l[4]); split_bf16(v1.y,h[5],l[5]);
    split_bf16(v1.z,h[6],l[6]); split_bf16(v1.w,h[7],l[7]);
    uint4 ph, pl;
    ph.x = pack16(h[0],h[1]); ph.y = pack16(h[2],h[3]);
    ph.z = pack16(h[4],h[5]); ph.w = pack16(h[6],h[7]);
    pl.x = pack16(l[0],l[1]); pl.y = pack16(l[2],l[3]);
    pl.z = pack16(l[4],l[5]); pl.w = pack16(l[6],l[7]);
    *(uint4*)(hi + base) = ph;
    *(uint4*)(lo + base) = pl;
}

// ---------------- pack streamed-W into per-(block,chunk) 8KB tiles -----------
__global__ __launch_bounds__(256)
void pack_wstr() {
    int gid = blockIdx.x * 256 + threadIdx.x;        // 2,097,152 16B-units
    int bk   = gid >> 14;
    int rem  = gid & 16383;
    int c    = rem >> 9;
    int rem2 = rem & 511;
    int r    = rem2 >> 3;
    int pu   = rem2 & 7;
    int u    = pu ^ (r & 7);
    int jbase = bk * 16;
    const bf16* src; int grow;
    if (r < 32)      { src = g_Whhb[1]; grow = (r >> 4) * Hh + jbase + (r & 15); }
    else if (r < 48) { src = g_Whhb[0]; grow = 2 * Hh + jbase + (r - 32); }
    else             { src = g_Whhb[1]; grow = 2 * Hh + jbase + (r - 48); }
    const uint4* s = (const uint4*)(src + (size_t)grow * Hh + c * 64 + u * 8);
    uint4* d = (uint4*)(g_WstrPk + ((size_t)(bk * 32 + c)) * 4096 + r * 64 + pu * 8);
    *d = *s;
}

// ---------------- 3-pass split-bf16 tensor-core GEMM (round-14 exact) --------
#define SLD 40
#define GEMM_SMEM (2 * 4 * 128 * SLD * 2)   // 81920 B

template<bool RELU, bool BF16OUT>
__global__ __launch_bounds__(256)
void gemm3p(const bf16* __restrict__ Ah, const bf16* __restrict__ Al,
            const bf16* __restrict__ Wh, const bf16* __restrict__ Wl,
            const float* __restrict__ bias,
            float* __restrict__ outF, bf16* __restrict__ outH, bf16* __restrict__ outL,
            int M, int N, int K) {
    extern __shared__ char raw[];
    uint16_t* sm = (uint16_t*)raw;
    const int tid = threadIdx.x, lane = tid & 31, wid = tid >> 5;
    const int wm = (wid & 3) * 32, wn = (wid >> 2) * 64;
    const int n0 = blockIdx.x * 128, m0 = blockIdx.y * 128;
    const int gr = lane >> 2, c2 = (lane & 3) * 2;
    const int row0 = tid >> 2, seg = (tid & 3) << 3;
    const uint32_t smBase = (uint32_t)__cvta_generic_to_shared(sm);

    const bf16* gAh = Ah + (size_t)m0 * K;
    const bf16* gAl = Al + (size_t)m0 * K;
    const bf16* gWh = Wh + (size_t)n0 * K;
    const bf16* gWl = Wl + (size_t)n0 * K;

    float acc[2][8][4];
#pragma unroll
    for (int i = 0; i < 2; i++)
#pragma unroll
        for (int j = 0; j < 8; j++)
#pragma unroll
            for (int e = 0; e < 4; e++) acc[i][j][e] = 0.0f;

#define GISS(ptr, aidx, rep, s, k0) \
    cp16(smBase + (uint32_t)((((s)*4+(aidx))*(128*SLD)) + (row0 + (rep)*64)*SLD + seg)*2, \
         (ptr) + (size_t)(row0 + (rep)*64) * K + (k0) + seg)
#define GEMM_ISSUE(s, k0) do { \
    GISS(gAh, 0, 0, s, k0); GISS(gAh, 0, 1, s, k0); \
    GISS(gAl, 1, 0, s, k0); GISS(gAl, 1, 1, s, k0); \
    GISS(gWh, 2, 0, s, k0); GISS(gWh, 2, 1, s, k0); \
    GISS(gWl, 3, 0, s, k0); GISS(gWl, 3, 1, s, k0); } while (0)

    const int nch = K >> 5;
    GEMM_ISSUE(0, 0);
    CP_COMMIT;
#pragma unroll 1
    for (int c = 0; c < nch; c++) {
        if (c + 1 < nch) { GEMM_ISSUE((c + 1) & 1, (c + 1) << 5); CP_COMMIT; CP_WAIT1; }
        else { CP_WAIT0; }
        __syncthreads();
        const int st = c & 1;
        const uint16_t* Ah_s = sm + (st * 4 + 0) * (128 * SLD);
        const uint16_t* Al_s = sm + (st * 4 + 1) * (128 * SLD);
        const uint16_t* Wh_s = sm + (st * 4 + 2) * (128 * SLD);
        const uint16_t* Wl_s = sm + (st * 4 + 3) * (128 * SLD);
#pragma unroll
        for (int ks = 0; ks < 2; ks++) {
            const int kb = ks * 16;
            uint32_t ahf[2][4], alf[2][4];
#pragma unroll
            for (int mt = 0; mt < 2; mt++) {
                ldsm4f(ahf[mt], Ah_s, SLD, wm + mt * 16, kb, lane);
                ldsm4f(alf[mt], Al_s, SLD, wm + mt * 16, kb, lane);
            }
#pragma unroll
            for (int p = 0; p < 4; p++) {
                uint32_t bh[4], bl[4];
                ldsm4f(bh, Wh_s, SLD, wn + p * 16, kb, lane);
                ldsm4f(bl, Wl_s, SLD, wn + p * 16, kb, lane);
#pragma unroll
                for (int e = 0; e < 2; e++) {
                    const int nt = p * 2 + e;
#pragma unroll
                    for (int mt = 0; mt < 2; mt++) {
                        MMA4(acc[mt][nt], ahf[mt], bh[e], bh[2 + e]);
                        MMA4(acc[mt][nt], ahf[mt], bl[e], bl[2 + e]);
                        MMA4(acc[mt][nt], alf[mt], bh[e], bh[2 + e]);
                    }
                }
            }
        }
        __syncthreads();
    }

#pragma unroll
    for (int mt = 0; mt < 2; mt++) {
        const int r = m0 + wm + mt * 16 + gr;
#pragma unroll
        for (int nt = 0; nt < 8; nt++) {
            const int cb = n0 + wn + nt * 8 + c2;
            float bx = bias[cb], by = bias[cb + 1];
            float v0 = acc[mt][nt][0] + bx;
            float v1 = acc[mt][nt][1] + by;
            float v2 = acc[mt][nt][2] + bx;
            float v3 = acc[mt][nt][3] + by;
            if (RELU) {
                v0 = fmaxf(v0, 0.0f); v1 = fmaxf(v1, 0.0f);
                v2 = fmaxf(v2, 0.0f); v3 = fmaxf(v3, 0.0f);
            }
            if (BF16OUT) {
                uint16_t h0,l0,h1,l1;
                split_bf16(v0,h0,l0); split_bf16(v1,h1,l1);
                *(uint32_t*)(outH + (size_t)r * N + cb) = pack16(h0,h1);
                *(uint32_t*)(outL + (size_t)r * N + cb) = pack16(l0,l1);
                split_bf16(v2,h0,l0); split_bf16(v3,h1,l1);
                *(uint32_t*)(outH + (size_t)(r + 8) * N + cb) = pack16(h0,h1);
                *(uint32_t*)(outL + (size_t)(r + 8) * N + cb) = pack16(l0,l1);
            } else {
                *(float2*)(outF + (size_t)r * N + cb)       = make_float2(v0, v1);
                *(float2*)(outF + (size_t)(r + 8) * N + cb) = make_float2(v2, v3);
            }
        }
    }
}

// ---------------- persistent GRU: 5-deep TMA pipeline (round-14 structure) ---
// 128 blocks x 384 threads. Gate phase remapped j-fastest for coalescing.
#define NST 5
#define RES_ELEMS 65536
#define STG_ELEMS 8192
#define STG_B 16384
#define GRU_SMEM ((RES_ELEMS + NST * STG_ELEMS) * 2 + 48 * 33 * 4)  // 219328

__global__ __launch_bounds__(384)
void gru_persist(const float* __restrict__ bhh) {
    extern __shared__ char raw[];
    uint16_t* sm = (uint16_t*)raw;
    __shared__ __align__(8) uint64_t s_mbar[NST];
    const int tid = threadIdx.x, lane = tid & 31, wid = tid >> 5;
    const int nt = wid % 6, mt = wid / 6;
    const int jbase = blockIdx.x * 16;
    const int gr = lane >> 2, cc2 = (lane & 3) * 2;
    const uint32_t smBase = (uint32_t)__cvta_generic_to_shared(sm);
    const uint32_t stgBase = smBase + RES_ELEMS * 2;
    float* hp = (float*)(raw + (RES_ELEMS + NST * STG_ELEMS) * 2);
    const uint32_t mbarBase = (uint32_t)__cvta_generic_to_shared(s_mbar);

    // prologue: pack resident W_{r,z} hi into chunk-major swizzled smem
    for (int i = tid; i < 8192; i += 384) {
        int c = i >> 8; int rem = i & 255;
        int r = rem >> 3; int pu = rem & 7;
        int u = pu ^ (r & 7);
        int grow = (r >> 4) * Hh + jbase + (r & 15);
        *(uint4*)(sm + (size_t)(c * 32 + r) * 64 + pu * 8) =
            *(const uint4*)(g_Whhb[0] + (size_t)grow * Hh + c * 64 + u * 8);
    }
    if (tid == 0) {
#pragma unroll
        for (int s = 0; s < NST; s++)
            asm volatile("mbarrier.init.shared.b64 [%0], 1;" :: "r"(mbarBase + s * 8) : "memory");
    }
    __syncthreads();

    const bf16* wstrB = g_WstrPk + (size_t)blockIdx.x * 32 * 4096;
    uint32_t phMask = 0;

    auto rearm = [&](int s) {
        asm volatile("mbarrier.arrive.expect_tx.shared.b64 _, [%0], %1;"
            :: "r"(mbarBase + s * 8), "r"((uint32_t)STG_B) : "memory");
    };
    auto issueW = [&](int s, int ch) {
        asm volatile("cp.async.bulk.shared::cta.global.mbarrier::complete_tx::bytes [%0], [%1], %2, [%3];"
            :: "r"(stgBase + s * STG_B), "l"((const void*)(wstrB + (size_t)ch * 4096)),
               "r"(8192u), "r"(mbarBase + s * 8) : "memory");
    };
    auto issueH = [&](int s, int ch, const bf16* hh, const bf16* hl) {
        asm volatile("cp.async.bulk.shared::cta.global.mbarrier::complete_tx::bytes [%0], [%1], %2, [%3];"
            :: "r"(stgBase + s * STG_B + 8192u), "l"((const void*)(hh + ch * 2048)),
               "r"(4096u), "r"(mbarBase + s * 8) : "memory");
        asm volatile("cp.async.bulk.shared::cta.global.mbarrier::complete_tx::bytes [%0], [%1], %2, [%3];"
            :: "r"(stgBase + s * STG_B + 12288u), "l"((const void*)(hl + ch * 2048)),
               "r"(4096u), "r"(mbarBase + s * 8) : "memory");
    };
    auto wait_stage = [&](int s) {
        uint32_t bar = mbarBase + s * 8;
        uint32_t p = (phMask >> s) & 1u;
        uint32_t done;
        do {
            asm volatile("{\n\t.reg .pred P;\n\t"
                "mbarrier.try_wait.parity.shared.b64 P, [%1], %2, 0x989680;\n\t"
                "selp.b32 %0, 1, 0, P;\n\t}"
                : "=r"(done) : "r"(bar), "r"(p) : "memory");
        } while (!done);
        phMask ^= (1u << s);
    };

    // step-0 prefetch: all 5 stages (W + h)
    if (tid == 0) {
        const bf16* h0 = g_hpk[0][0];
        const bf16* l0 = g_hpk[0][1];
#pragma unroll
        for (int s = 0; s < NST; s++) { rearm(s); issueW(s, s); issueH(s, s, h0, l0); }
    }

#pragma unroll 1
    for (int t = 0; t < Tt; t++) {
        const bf16* hHi = g_hpk[t & 1][0];
        const bf16* hLo = g_hpk[t & 1][1];

        float accA[4] = {0.f, 0.f, 0.f, 0.f};
        float accB[4] = {0.f, 0.f, 0.f, 0.f};
        float accC[4] = {0.f, 0.f, 0.f, 0.f};
        int s = 0;
#pragma unroll 1
        for (int c = 0; c < 32; c++) {
            wait_stage(s);
            const uint16_t* Wst  = sm + RES_ELEMS + s * STG_ELEMS;
            const uint16_t* WnHi = Wst + 2048;
            const uint16_t* WnLo = Wst + 3072;
            const uint16_t* Hh_s = Wst + 4096;
            const uint16_t* Hl_s = Wst + 6144;
            const uint16_t* Wres = sm + c * 2048;
#pragma unroll
            for (int ks = 0; ks < 4; ks++) {
                const int kb = ks * 16;
                uint32_t ah[4], al[4], bh[2], bl[2];
                ldsm4_sw(ah, Hh_s, mt * 16, kb, lane);
                ldsm4_sw(al, Hl_s, mt * 16, kb, lane);
                if (nt < 4) {
                    ldsm2_sw(bh, Wres, nt * 8, kb, lane);
                    ldsm2_sw(bl, Wst,  nt * 8, kb, lane);
                } else {
                    ldsm2_sw(bh, WnHi, (nt - 4) * 8, kb, lane);
                    ldsm2_sw(bl, WnLo, (nt - 4) * 8, kb, lane);
                }
                MMA4(accA, ah, bh[0], bh[1]);
                MMA4(accB, ah, bl[0], bl[1]);
                MMA4(accC, al, bh[0], bh[1]);
            }
            __syncthreads();
            if (tid == 0) {
                int n = c + NST;
                if (n < 32) { rearm(s); issueW(s, n); issueH(s, n, hHi, hLo); }
                else if (t < Tt - 1) { rearm(s); issueW(s, s); }   // next step chunk s
            }
            s = (s == NST - 1) ? 0 : s + 1;
        }

        // combine passes, scatter into hp[gate_row][batch], stride 33
        {
            int col = nt * 8 + cc2, row = mt * 16 + gr;
            hp[col * 33 + row]           = accA[0] + accB[0] + accC[0];
            hp[(col + 1) * 33 + row]     = accA[1] + accB[1] + accC[1];
            hp[col * 33 + row + 8]       = accA[2] + accB[2] + accC[2];
            hp[(col + 1) * 33 + row + 8] = accA[3] + accB[3] + accC[3];
        }
        __syncthreads();

        // ---- gate phase: j-fastest mapping for coalesced global access ----
        const float* HTprev = g_HT[t & 1];
        float* HTnext = g_HT[(t & 1) ^ 1];
        bf16* nHi = g_hpk[(t & 1) ^ 1][0];
        bf16* nLo = g_hpk[(t & 1) ^ 1][1];
#pragma unroll
        for (int i = 0; i < 2; i++) {
            int oi = tid + i * 384;
            if (oi < 512) {
                int jj = oi & 15, b = oi >> 4, j = jbase + jj;
                size_t xoff = ((size_t)b * Tt + t) * G3 + j;
                float xr = g_XP[xoff];
                float xz = g_XP[xoff + Hh];
                float xn = g_XP[xoff + 2 * Hh];
                float hr = hp[jj * 33 + b]        + bhh[j];
                float hz = hp[(16 + jj) * 33 + b] + bhh[Hh + j];
                float hn = hp[(32 + jj) * 33 + b] + bhh[2 * Hh + j];
                float r = sigmoidf_(xr + hr);
                float z = sigmoidf_(xz + hz);
                float n = tanhf(xn + r * hn);
                float hprev = HTprev[(size_t)b * Hh + j];
                float hnew = (1.0f - z) * n + z * hprev;
                HTnext[(size_t)b * Hh + j] = hnew;
                uint16_t hh, hl;
                split_bf16(hnew, hh, hl);
                int ck = j >> 6, k = j & 63, u = k >> 3;
                size_t e = ((size_t)((ck << 5) + b) << 6) +
                           (size_t)(((u ^ (b & 7)) << 3) + (k & 7));
                nHi[e] = __ushort_as_bfloat16(hh);
                nLo[e] = __ushort_as_bfloat16(hl);
                g_Hb[0][((size_t)b * Tt + t) * Hh + j] = __ushort_as_bfloat16(hh);
                g_Hb[1][((size_t)b * Tt + t) * Hh + j] = __ushort_as_bfloat16(hl);
            }
        }

        // global barrier between steps (order gate writes before next h TMAs)
        asm volatile("fence.proxy.async;" ::: "memory");
        __threadfence();
        __syncthreads();
        if (tid == 0) {
            unsigned a = atomicAdd(&g_count, 1u);
            if (a == 127u) {
                g_count = 0u;
                __threadfence();
                atomicAdd(&g_gen, 1u);
            } else {
                while (*(volatile unsigned*)&g_gen <= (unsigned)t) __nanosleep(32);
            }
            // release h TMAs for next step's chunks 0..4 (W already in flight)
            if (t < Tt - 1) {
                const bf16* nh = g_hpk[(t + 1) & 1][0];
                const bf16* nl = g_hpk[(t + 1) & 1][1];
#pragma unroll
                for (int s2 = 0; s2 < NST; s2++) issueH(s2, s2, nh, nl);
            }
        }
        __syncthreads();
    }
}

// ---------------- heads ------------------------------------------------------
__global__ __launch_bounds__(128)
void heads_kernel(const int* __restrict__ labels,
                  const float* __restrict__ W4, const float* __restrict__ b4,
                  const float* __restrict__ W5, const float* __restrict__ b5,
                  const float* __restrict__ W6, const float* __restrict__ b6,
                  const float* __restrict__ Wp, const float* __restrict__ bp,
                  float* __restrict__ out) {
    const int bt   = blockIdx.x;
    const int b    = bt >> 7;
    const int t    = bt & 127;
    const int lane = threadIdx.x & 31;
    const int w    = threadIdx.x >> 5;
    const int lab  = labels[b];
    const float4* s4 = (const float4*)(g_S + (size_t)bt * PEN);

    for (int hh = w; hh < 7; hh += 4) {
        const float* Wrow;
        float bias;
        if (hh == 0)      { Wrow = W4 + (size_t)lab * PEN; bias = b4[lab]; }
        else if (hh == 1) { Wrow = W5 + (size_t)lab * PEN; bias = b5[lab]; }
        else if (hh == 2) { Wrow = W6 + (size_t)lab * PEN; bias = b6[lab]; }
        else {
            int p = hh - 3;
            Wrow = Wp + ((size_t)p * Cc + lab) * PEN;
            bias = bp[p * Cc + lab];
        }
        const float4* w4 = (const float4*)Wrow;
        float acc = 0.0f;
        for (int q = lane; q < PEN / 4; q += 32) {
            float4 sv = s4[q];
            float4 wv = w4[q];
            acc += sv.x * wv.x + sv.y * wv.y + sv.z * wv.z + sv.w * wv.w;
        }
#pragma unroll
        for (int off = 16; off > 0; off >>= 1)
            acc += __shfl_down_sync(0xffffffffu, acc, off);
        if (lane == 0) {
            float v = acc + bias;
            if (hh < 3) out[hh * BT + bt] = v;
            else {
                int p = hh - 3;
                out[3 * BT + ((size_t)p * Bb + b) * Tt + t] = 1.0f / (1.0f + expf(-v));
            }
        }
    }
}

// ---------------- launch -----------------------------------------------------
extern "C" void kernel_launch(void* const* d_in, const int* in_sizes, int n_in,
                              void* d_out, int out_size) {
    const float* x    = (const float*)d_in[0];
    const int*   lab  = (const int*)  d_in[1];
    const float* W1   = (const float*)d_in[2];
    const float* b1   = (const float*)d_in[3];
    const float* W2   = (const float*)d_in[4];
    const float* b2   = (const float*)d_in[5];
    const float* W_ih = (const float*)d_in[6];
    const float* b_ih = (const float*)d_in[7];
    const float* W_hh = (const float*)d_in[8];
    const float* b_hh = (const float*)d_in[9];
    const float* W3   = (const float*)d_in[10];
    const float* b3   = (const float*)d_in[11];
    const float* W4   = (const float*)d_in[12];
    const float* b4   = (const float*)d_in[13];
    const float* W5   = (const float*)d_in[14];
    const float* b5   = (const float*)d_in[15];
    const float* W6   = (const float*)d_in[16];
    const float* b6   = (const float*)d_in[17];
    const float* Wp   = (const float*)d_in[18];
    const float* bp   = (const float*)d_in[19];
    float* out = (float*)d_out;

    float *XP, *S;
    bf16 *xb[2], *W1b[2], *W2b[2], *Wihb[2], *W3b[2], *A1b[2], *A2b[2], *Hbp[2];
    cudaGetSymbolAddress((void**)&XP, g_XP);
    cudaGetSymbolAddress((void**)&S,  g_S);
    {
        char* p;
        cudaGetSymbolAddress((void**)&p, g_xb);
        xb[0] = (bf16*)p; xb[1] = xb[0] + BT * DIN;
        cudaGetSymbolAddress((void**)&p, g_W1b);
        W1b[0] = (bf16*)p; W1b[1] = W1b[0] + H1 * DIN;
        cudaGetSymbolAddress((void**)&p, g_W2b);
        W2b[0] = (bf16*)p; W2b[1] = W2b[0] + (size_t)Hh * H1;
        cudaGetSymbolAddress((void**)&p, g_Wihb);
        Wihb[0] = (bf16*)p; Wihb[1] = Wihb[0] + (size_t)G3 * Hh;
        cudaGetSymbolAddress((void**)&p, g_W3b);
        W3b[0] = (bf16*)p; W3b[1] = W3b[0] + (size_t)PEN * Hh;
        cudaGetSymbolAddress((void**)&p, g_A1b);
        A1b[0] = (bf16*)p; A1b[1] = A1b[0] + (size_t)BT * H1;
        cudaGetSymbolAddress((void**)&p, g_A2b);
        A2b[0] = (bf16*)p; A2b[1] = A2b[0] + (size_t)BT * Hh;
        cudaGetSymbolAddress((void**)&p, g_Hb);
        Hbp[0] = (bf16*)p; Hbp[1] = Hbp[0] + (size_t)BT * Hh;
    }

    cudaFuncSetAttribute(gemm3p<true,  true >, cudaFuncAttributeMaxDynamicSharedMemorySize, GEMM_SMEM);
    cudaFuncSetAttribute(gemm3p<false, false>, cudaFuncAttributeMaxDynamicSharedMemorySize, GEMM_SMEM);
    cudaFuncSetAttribute(gemm3p<true,  false>, cudaFuncAttributeMaxDynamicSharedMemorySize, GEMM_SMEM);
    cudaFuncSetAttribute(gru_persist, cudaFuncAttributeMaxDynamicSharedMemorySize, GRU_SMEM);

    // launch 0: all conversions + init (fused)
    convert_all<<<CONV_BLOCKS, 256>>>(x, W1, W2, W_ih, W_hh, W3, out, out_size);
    // launch 1: pack streamed GRU weights
    pack_wstr<<<8192, 256>>>();
    // launch 2: layer1
    gemm3p<true, true><<<dim3(H1 / 128, BT / 128), 256, GEMM_SMEM>>>(
        xb[0], xb[1], W1b[0], W1b[1], b1, nullptr, A1b[0], A1b[1], BT, H1, DIN);
    // launch 3: layer2
    gemm3p<true, true><<<dim3(Hh / 128, BT / 128), 256, GEMM_SMEM>>>(
        A1b[0], A1b[1], W2b[0], W2b[1], b2, nullptr, A2b[0], A2b[1], BT, Hh, H1);
    // launch 4: xp
    gemm3p<false, false><<<dim3(G3 / 128, BT / 128), 256, GEMM_SMEM>>>(
        A2b[0], A2b[1], Wihb[0], Wihb[1], b_ih, XP, nullptr, nullptr, BT, G3, Hh);
    // launch 5: GRU (profiler target)
    gru_persist<<<128, 384, GRU_SMEM>>>(b_hh);
    // launch 6: layer3
    gemm3p<true, false><<<dim3(PEN / 128, BT / 128), 256, GEMM_SMEM>>>(
        Hbp[0], Hbp[1], W3b[0], W3b[1], b3, S, nullptr, nullptr, BT, PEN, Hh);
    // launch 7: heads
    heads_kernel<<<BT, 128>>>(lab, W4, b4, W5, b5, W6, b6, Wp, bp, out);
}